// round 4
// baseline (speedup 1.0000x reference)
#include <cuda_runtime.h>
#include <math.h>

// Problem constants (fixed shapes)
#define Nn 8192
#define Ee 131072
#define Cc 64
#define NELn 10
#define NBn 8
#define Gg 32
#define Hh 16
#define RMAXf 5.0f
#define AVGf 16.0f
#define TBINS 8192
#define NODES 8   // nodes per block in the node kernels

// Scratch (device globals; no dynamic allocation allowed)
__device__ float g_h0[Nn * Cc];
__device__ int   g_elem[Nn];
__device__ float g_A[Nn * 4 * Cc];
__device__ float g_A2[Nn * 4 * Cc];
__device__ float g_out0[Nn * Cc];
__device__ float g_out1[Nn * 3 * Cc];
__device__ float g_d1[Nn * 3];
// Radial-MLP lookup tables (lerp over r in [0,RMAX]); 128 outputs per bin
__device__ float g_tab1[(TBINS + 8) * 128];
__device__ float g_tab2[(TBINS + 8) * 128];

// ---------------------------------------------------------------------------
__global__ void k_zero(float* __restrict__ out_tot) {
    int i = blockIdx.x * blockDim.x + threadIdx.x;
    int stride = gridDim.x * blockDim.x;
    const int tot = Nn * 4 * Cc;
    for (int j = i; j < tot; j += stride) {
        g_A[j]  = 0.0f;
        g_A2[j] = 0.0f;
    }
    if (i < Gg * 3) out_tot[i] = 0.0f;
}

// ---------------------------------------------------------------------------
__global__ void k_h0(const float* __restrict__ na, const float* __restrict__ We) {
    int n = blockIdx.x;
    int c = threadIdx.x;
    float acc = 0.0f;
#pragma unroll
    for (int k = 0; k < NELn; k++)
        acc = fmaf(na[n * NELn + k], We[k * Cc + c], acc);
    g_h0[n * Cc + c] = acc;
    if (c == 0) {
        int best = 0;
        float bv = na[n * NELn];
#pragma unroll
        for (int k = 1; k < NELn; k++) {
            float v = na[n * NELn + k];
            if (v > bv) { bv = v; best = k; }
        }
        g_elem[n] = best;
    }
}

// ---------------------------------------------------------------------------
// Radial-MLP lookup-table build (w(r) is a smooth function of r only).
// ---------------------------------------------------------------------------
__global__ void k_table(const float* __restrict__ Wa1, const float* __restrict__ Wb1,
                        const float* __restrict__ Wa2, const float* __restrict__ Wb2) {
    int bin  = blockIdx.x;               // 0..TBINS
    int pass = blockIdx.y;
    const float* Wa = pass ? Wa2 : Wa1;
    const float* Wb = pass ? Wb2 : Wb1;
    float* tab      = pass ? g_tab2 : g_tab1;
    int c = threadIdx.x;                 // 0..127

    float r = fmaxf((float)bin * (RMAXf / (float)TBINS), 1e-6f);
    float x = r * (1.0f / RMAXf);
    float x2 = x * x;
    float x5 = x2 * x2 * x;
    float env = 1.0f - 21.0f * x5 + 35.0f * x5 * x - 15.0f * x5 * x2;
    if (x >= 1.0f) env = 0.0f;

    float pref = sqrtf(2.0f / RMAXf) * env / r;
    float wphase = (3.14159265358979323846f / RMAXf) * r;

    __shared__ float hid[Cc];
    if (c < Cc) {
        float h = 0.0f;
#pragma unroll
        for (int nb = 0; nb < NBn; nb++) {
            float rbn = pref * sinf((float)(nb + 1) * wphase);
            h = fmaf(rbn, Wa[nb * Cc + c], h);
        }
        hid[c] = h / (1.0f + expf(-h));
    }
    __syncthreads();

    float acc = 0.0f;
#pragma unroll
    for (int k = 0; k < Cc; k++)
        acc = fmaf(hid[k], Wb[k * 256 + c], acc);
    tab[bin * 128 + c] = acc;
}

// ---------------------------------------------------------------------------
// Edge kernel (warp-per-edge, lerp-table radial weights).
// ---------------------------------------------------------------------------
__global__ void k_edge(const float* __restrict__ pos,
                       const float* __restrict__ shifts,
                       const int* __restrict__ ei,
                       int pass) {
    int gw = (blockIdx.x * blockDim.x + threadIdx.x) >> 5;
    int lane = threadIdx.x & 31;
    if (gw >= Ee) return;

    const float* feat = pass ? g_out0 : g_h0;
    const float* tab  = pass ? g_tab2 : g_tab1;
    float* Aout       = pass ? g_A2   : g_A;

    int snd = ei[gw];
    int rcv = ei[Ee + gw];

    float vx = pos[rcv * 3 + 0] - pos[snd * 3 + 0] + shifts[gw * 3 + 0];
    float vy = pos[rcv * 3 + 1] - pos[snd * 3 + 1] + shifts[gw * 3 + 1];
    float vz = pos[rcv * 3 + 2] - pos[snd * 3 + 2] + shifts[gw * 3 + 2];
    float r  = sqrtf(vx * vx + vy * vy + vz * vz + 1e-12f);
    if (r >= RMAXf) return;

    float t = r * ((float)TBINS / RMAXf);
    int   i = (int)t;
    float f = t - (float)i;
    const float* row = tab + i * 128;

    int c0 = lane, c1 = lane + 32;
    float w0a = row[c0]      + (row[128 + c0]      - row[c0])      * f;
    float w0b = row[c1]      + (row[128 + c1]      - row[c1])      * f;
    float w1a = row[c0 + 64] + (row[192 + c0]      - row[c0 + 64]) * f;
    float w1b = row[c1 + 64] + (row[192 + c1]      - row[c1 + 64]) * f;

    float fsa = feat[snd * Cc + c0];
    float fsb = feat[snd * Cc + c1];

    const float s3 = 1.7320508075688772f;
    float irs = s3 / r;
    float ga = fsa * w1a * irs;
    float gb = fsb * w1b * irs;

    float* base = Aout + rcv * (4 * Cc);
    atomicAdd(base + c0,          fsa * w0a);
    atomicAdd(base + c1,          fsb * w0b);
    atomicAdd(base + Cc + c0,     ga * vx);
    atomicAdd(base + Cc + c1,     gb * vx);
    atomicAdd(base + 2 * Cc + c0, ga * vy);
    atomicAdd(base + 2 * Cc + c1, gb * vy);
    atomicAdd(base + 3 * Cc + c0, ga * vz);
    atomicAdd(base + 3 * Cc + c1, gb * vz);
}

// ---------------------------------------------------------------------------
// Node layer 1, batched NODES nodes per block (64 threads = out channel d).
// Weight LDGs amortized across the NODES nodes.
// ---------------------------------------------------------------------------
__global__ void __launch_bounds__(64) k_node1(
        const float* __restrict__ Wmix1,
        const float* __restrict__ Wsc1,
        const float* __restrict__ Wps,
        const float* __restrict__ Wpv,
        const float* __restrict__ Wp10,
        const float* __restrict__ Wp11,
        const float* __restrict__ wread1)
{
    int nb = blockIdx.x * NODES;
    int d = threadIdx.x;
    __shared__ float Ar[NODES][4][Cc];
    __shared__ float h0s[NODES][Cc];
    __shared__ float m0s[NODES][Cc];
    __shared__ float tm[NODES][3][Cc];
    __shared__ int   els[NODES];
    __shared__ float red[NODES][3][2];

    const float ia = 1.0f / AVGf;
#pragma unroll
    for (int j = 0; j < NODES; j++) {
#pragma unroll
        for (int k = 0; k < 4; k++)
            Ar[j][k][d] = g_A[(nb + j) * 256 + k * Cc + d] * ia;
        h0s[j][d] = g_h0[(nb + j) * Cc + d];
    }
    if (d < NODES) els[d] = g_elem[nb + d];
    __syncthreads();

    // h1[k] = Ar[k] @ Wmix[L_OF[k]]  (L_OF[0..3] = 0,1,1,1)
    float a0[NODES], a1[NODES], a2[NODES], a3[NODES];
#pragma unroll
    for (int j = 0; j < NODES; j++) { a0[j] = a1[j] = a2[j] = a3[j] = 0.0f; }
#pragma unroll 4
    for (int c = 0; c < Cc; c++) {
        float w0 = Wmix1[c * Cc + d];
        float w1 = Wmix1[Cc * Cc + c * Cc + d];
#pragma unroll
        for (int j = 0; j < NODES; j++) {
            a0[j] = fmaf(Ar[j][0][c], w0, a0[j]);
            a1[j] = fmaf(Ar[j][1][c], w1, a1[j]);
            a2[j] = fmaf(Ar[j][2][c], w1, a2[j]);
            a3[j] = fmaf(Ar[j][3][c], w1, a3[j]);
        }
    }

    // polynomial gates (per-element weights)
#pragma unroll
    for (int j = 0; j < NODES; j++) {
        int el = els[j];
        float s = a0[j];
        float ws0 = Wps[el * Cc + d];
        float ws1 = Wps[NELn * Cc + el * Cc + d];
        float ws2 = Wps[2 * NELn * Cc + el * Cc + d];
        float wv0 = Wpv[el * Cc + d];
        float wv1 = Wpv[NELn * Cc + el * Cc + d];
        float wv2 = Wpv[2 * NELn * Cc + el * Cc + d];
        float m0 = s * (ws0 + s * (ws1 + s * ws2));
        float gv = wv0 + s * (wv1 + s * wv2);
        m0s[j][d]   = m0;
        tm[j][0][d] = a1[j] * gv;
        tm[j][1][d] = a2[j] * gv;
        tm[j][2][d] = a3[j] * gv;
    }
    __syncthreads();

    // out0 = m0 @ Wp1_0 + h0 @ Wsc1[el]
    float o0[NODES];
#pragma unroll
    for (int j = 0; j < NODES; j++) o0[j] = 0.0f;
#pragma unroll 4
    for (int c = 0; c < Cc; c++) {
        float wp = Wp10[c * Cc + d];
#pragma unroll
        for (int j = 0; j < NODES; j++)
            o0[j] = fmaf(m0s[j][c], wp, o0[j]);
    }
#pragma unroll
    for (int j = 0; j < NODES; j++) {
        const float* Ws = Wsc1 + els[j] * Cc * Cc;
        float acc = o0[j];
#pragma unroll 4
        for (int c = 0; c < Cc; c++)
            acc = fmaf(h0s[j][c], Ws[c * Cc + d], acc);
        g_out0[(nb + j) * Cc + d] = acc;
    }

    // out1 = (h1[1:4] * gv) @ Wp1_1 ;  d1 = out1 . w_read1
    float o1[NODES][3];
#pragma unroll
    for (int j = 0; j < NODES; j++) { o1[j][0] = o1[j][1] = o1[j][2] = 0.0f; }
#pragma unroll 4
    for (int c = 0; c < Cc; c++) {
        float wp = Wp11[c * Cc + d];
#pragma unroll
        for (int j = 0; j < NODES; j++) {
            o1[j][0] = fmaf(tm[j][0][c], wp, o1[j][0]);
            o1[j][1] = fmaf(tm[j][1][c], wp, o1[j][1]);
            o1[j][2] = fmaf(tm[j][2][c], wp, o1[j][2]);
        }
    }
    float wr = wread1[d];
#pragma unroll
    for (int j = 0; j < NODES; j++) {
#pragma unroll
        for (int m = 0; m < 3; m++) {
            g_out1[((nb + j) * 3 + m) * Cc + d] = o1[j][m];
            float v = o1[j][m] * wr;
            v += __shfl_down_sync(0xffffffffu, v, 16);
            v += __shfl_down_sync(0xffffffffu, v, 8);
            v += __shfl_down_sync(0xffffffffu, v, 4);
            v += __shfl_down_sync(0xffffffffu, v, 2);
            v += __shfl_down_sync(0xffffffffu, v, 1);
            if ((d & 31) == 0) red[j][m][d >> 5] = v;
        }
    }
    __syncthreads();
    if (d < NODES * 3) {
        int j = d / 3, m = d % 3;
        g_d1[(nb + j) * 3 + m] = red[j][m][0] + red[j][m][1];
    }
}

// ---------------------------------------------------------------------------
// Node layer 2, batched NODES nodes per block.
// ---------------------------------------------------------------------------
__global__ void __launch_bounds__(64) k_node2(
        const float* __restrict__ Wmix2,
        const float* __restrict__ Wsc2,
        const float* __restrict__ Wprod2,
        const float* __restrict__ Wp2,
        const float* __restrict__ Wv,
        const float* __restrict__ Wg1,
        const float* __restrict__ bg1,
        const float* __restrict__ Wg2,
        const float* __restrict__ bg2,
        const float* __restrict__ wread2,
        const int* __restrict__ batch,
        const float* __restrict__ charges,
        const float* __restrict__ pos,
        float* __restrict__ out)
{
    int nb = blockIdx.x * NODES;
    int d = threadIdx.x;
    __shared__ float Ar[NODES][4][Cc];
    __shared__ float o1s[NODES][3][Cc];
    __shared__ float tm[NODES][3][Cc];
    __shared__ float o2s[NODES][3][Cc];
    __shared__ float vhs[NODES][3][Hh];
    __shared__ float invs[NODES][Hh];
    __shared__ float g1s[NODES][Hh];
    __shared__ float af[NODES][Hh];
    __shared__ int   els[NODES];

    const float ia = 1.0f / AVGf;
#pragma unroll
    for (int j = 0; j < NODES; j++) {
#pragma unroll
        for (int k = 0; k < 4; k++)
            Ar[j][k][d] = g_A2[(nb + j) * 256 + k * Cc + d] * ia;
#pragma unroll
        for (int m = 0; m < 3; m++)
            o1s[j][m][d] = g_out1[((nb + j) * 3 + m) * Cc + d];
    }
    if (d < NODES) els[d] = g_elem[nb + d];
    __syncthreads();

    // h2
    float a0[NODES], a1[NODES], a2[NODES], a3[NODES];
#pragma unroll
    for (int j = 0; j < NODES; j++) { a0[j] = a1[j] = a2[j] = a3[j] = 0.0f; }
#pragma unroll 4
    for (int c = 0; c < Cc; c++) {
        float w0 = Wmix2[c * Cc + d];
        float w1 = Wmix2[Cc * Cc + c * Cc + d];
#pragma unroll
        for (int j = 0; j < NODES; j++) {
            a0[j] = fmaf(Ar[j][0][c], w0, a0[j]);
            a1[j] = fmaf(Ar[j][1][c], w1, a1[j]);
            a2[j] = fmaf(Ar[j][2][c], w1, a2[j]);
            a3[j] = fmaf(Ar[j][3][c], w1, a3[j]);
        }
    }

#pragma unroll
    for (int j = 0; j < NODES; j++) {
        int el = els[j];
        float s2 = a0[j];
        float wv0 = Wprod2[el * Cc + d];
        float wv1 = Wprod2[NELn * Cc + el * Cc + d];
        float wv2 = Wprod2[2 * NELn * Cc + el * Cc + d];
        float gv2 = wv0 + s2 * (wv1 + s2 * wv2);
        tm[j][0][d] = a1[j] * gv2;
        tm[j][1][d] = a2[j] * gv2;
        tm[j][2][d] = a3[j] * gv2;
    }
    __syncthreads();

    // out2 = tm @ Wp2 + o1 @ Wsc2[el]
    float o2[NODES][3];
#pragma unroll
    for (int j = 0; j < NODES; j++) { o2[j][0] = o2[j][1] = o2[j][2] = 0.0f; }
#pragma unroll 4
    for (int c = 0; c < Cc; c++) {
        float wp = Wp2[c * Cc + d];
#pragma unroll
        for (int j = 0; j < NODES; j++) {
            o2[j][0] = fmaf(tm[j][0][c], wp, o2[j][0]);
            o2[j][1] = fmaf(tm[j][1][c], wp, o2[j][1]);
            o2[j][2] = fmaf(tm[j][2][c], wp, o2[j][2]);
        }
    }
#pragma unroll
    for (int j = 0; j < NODES; j++) {
        const float* Ws = Wsc2 + els[j] * Cc * Cc;
        float s0 = o2[j][0], s1 = o2[j][1], s2 = o2[j][2];
#pragma unroll 4
        for (int c = 0; c < Cc; c++) {
            float w = Ws[c * Cc + d];   // amortized across m
            s0 = fmaf(o1s[j][0][c], w, s0);
            s1 = fmaf(o1s[j][1][c], w, s1);
            s2 = fmaf(o1s[j][2][c], w, s2);
        }
        o2s[j][0][d] = s0;
        o2s[j][1][d] = s1;
        o2s[j][2][d] = s2;
    }
    __syncthreads();

    // vh[j][m][h] = out2[j][m] @ Wv   (NODES*3*16 = 384 outputs)
#pragma unroll
    for (int t = d; t < NODES * 3 * Hh; t += Cc) {
        int j = t / (3 * Hh);
        int r = t - j * 3 * Hh;
        int m = r >> 4, h = r & 15;
        float acc = 0.0f;
#pragma unroll 4
        for (int c = 0; c < Cc; c++)
            acc = fmaf(o2s[j][m][c], Wv[c * Hh + h], acc);
        vhs[j][m][h] = acc;
    }
    __syncthreads();

    // invariants
#pragma unroll
    for (int t = d; t < NODES * Hh; t += Cc) {
        int j = t >> 4, h = t & 15;
        float v0 = vhs[j][0][h], v1 = vhs[j][1][h], v2 = vhs[j][2][h];
        invs[j][h] = sqrtf(v0 * v0 + v1 * v1 + v2 * v2 + 1e-12f);
    }
    __syncthreads();

    // gate MLP layer 1 (silu)
#pragma unroll
    for (int t = d; t < NODES * Hh; t += Cc) {
        int j = t >> 4, h = t & 15;
        float pre = bg1[h];
#pragma unroll
        for (int hh = 0; hh < Hh; hh++)
            pre = fmaf(invs[j][hh], Wg1[hh * Hh + h], pre);
        g1s[j][h] = pre / (1.0f + expf(-pre));
    }
    __syncthreads();

    // gate MLP layer 2 * w_read2
#pragma unroll
    for (int t = d; t < NODES * Hh; t += Cc) {
        int j = t >> 4, h = t & 15;
        float a = bg2[h];
#pragma unroll
        for (int hh = 0; hh < Hh; hh++)
            a = fmaf(g1s[j][hh], Wg2[hh * Hh + h], a);
        af[j][h] = a * wread2[h];
    }
    __syncthreads();

    // dipoles + per-graph totals
    if (d < NODES * 3) {
        int j = d / 3, m = d % 3;
        int n = nb + j;
        float d2 = 0.0f;
#pragma unroll
        for (int h = 0; h < Hh; h++)
            d2 = fmaf(vhs[j][m][h], af[j][h], d2);
        float dip = g_d1[n * 3 + m] + d2;
        out[Gg * 3 + n * 3 + m] = dip;
        int g = batch[n];
        atomicAdd(&out[g * 3 + m], dip + charges[n] * pos[n * 3 + m]);
    }
}

// ---------------------------------------------------------------------------
// Host launcher
// ---------------------------------------------------------------------------
extern "C" void kernel_launch(void* const* d_in, const int* in_sizes, int n_in,
                              void* d_out, int out_size) {
    int iei = -1;
    for (int i = 0; i < n_in; i++) {
        if (in_sizes[i] == 2 * Ee) { iei = i; break; }
    }
    if (iei < 0) iei = 4;

    const float* na      = (const float*)d_in[0];
    const float* pos     = (const float*)d_in[1];
    const float* shifts  = (const float*)d_in[2];
    const float* charges = (const float*)d_in[3];
    const int*   ei      = (const int*)d_in[iei];
    const int*   batch   = (const int*)d_in[iei + 1];

    int w;
    if (iei == 4) {
        w = (n_in > 6 && in_sizes[6] == 1) ? 7 : 6;
    } else {
        w = 4;
    }

    const float* W_embed = (const float*)d_in[w + 0];
    const float* Wr1a    = (const float*)d_in[w + 1];
    const float* Wr1b    = (const float*)d_in[w + 2];
    const float* Wmix1   = (const float*)d_in[w + 3];
    const float* Wsc1    = (const float*)d_in[w + 4];
    const float* Wp1s    = (const float*)d_in[w + 5];
    const float* Wp1v    = (const float*)d_in[w + 6];
    const float* Wp10    = (const float*)d_in[w + 7];
    const float* Wp11    = (const float*)d_in[w + 8];
    const float* wread1  = (const float*)d_in[w + 9];
    const float* Wr2a    = (const float*)d_in[w + 10];
    const float* Wr2b    = (const float*)d_in[w + 11];
    const float* Wmix2   = (const float*)d_in[w + 12];
    const float* Wsc2    = (const float*)d_in[w + 13];
    const float* Wprod2  = (const float*)d_in[w + 14];
    const float* Wp2     = (const float*)d_in[w + 15];
    const float* Wv      = (const float*)d_in[w + 16];
    const float* Wg1     = (const float*)d_in[w + 17];
    const float* bg1     = (const float*)d_in[w + 18];
    const float* Wg2     = (const float*)d_in[w + 19];
    const float* bg2     = (const float*)d_in[w + 20];
    const float* wread2  = (const float*)d_in[w + 21];

    float* out = (float*)d_out;

    k_zero<<<2048, 256>>>(out);
    k_h0<<<Nn, Cc>>>(na, W_embed);
    dim3 tg(TBINS + 1, 2);
    k_table<<<tg, 128>>>(Wr1a, Wr1b, Wr2a, Wr2b);
    k_edge<<<Ee / 8, 256>>>(pos, shifts, ei, 0);
    k_node1<<<Nn / NODES, Cc>>>(Wmix1, Wsc1, Wp1s, Wp1v, Wp10, Wp11, wread1);
    k_edge<<<Ee / 8, 256>>>(pos, shifts, ei, 1);
    k_node2<<<Nn / NODES, Cc>>>(Wmix2, Wsc2, Wprod2, Wp2, Wv, Wg1, bg1, Wg2, bg2,
                                wread2, batch, charges, pos, out);
}

// round 5
// speedup vs baseline: 1.3443x; 1.3443x over previous
#include <cuda_runtime.h>
#include <math.h>

// Problem constants (fixed shapes)
#define Nn 8192
#define Ee 131072
#define Cc 64
#define NELn 10
#define NBn 8
#define Gg 32
#define Hh 16
#define RMAXf 5.0f
#define AVGf 16.0f
#define TBINS 8192

// Scratch (device globals; no dynamic allocation allowed)
__device__ __align__(16) float g_h0[Nn * Cc];
__device__ int   g_elem[Nn];
__device__ __align__(16) float g_A[Nn * 4 * Cc];
__device__ __align__(16) float g_A2[Nn * 4 * Cc];
__device__ __align__(16) float g_out0[Nn * Cc];
__device__ __align__(16) float g_out1[Nn * 3 * Cc];
__device__ float g_d1[Nn * 3];
// Radial-MLP lookup tables (lerp over r in [0,RMAX]); 128 outputs per bin
__device__ __align__(16) float g_tab1[(TBINS + 8) * 128];
__device__ __align__(16) float g_tab2[(TBINS + 8) * 128];

// Vectorized global float4 reduction (PTX 8.1+, sm_90+)
__device__ __forceinline__ void red4(float* p, float a, float b, float c, float d) {
    asm volatile("red.global.add.v4.f32 [%0], {%1, %2, %3, %4};"
                 :: "l"(p), "f"(a), "f"(b), "f"(c), "f"(d) : "memory");
}

// ---------------------------------------------------------------------------
__global__ void k_zero(float* __restrict__ out_tot) {
    int i = blockIdx.x * blockDim.x + threadIdx.x;
    int stride = gridDim.x * blockDim.x;
    const int tot = Nn * 4 * Cc;
    for (int j = i; j < tot; j += stride) {
        g_A[j]  = 0.0f;
        g_A2[j] = 0.0f;
    }
    if (i < Gg * 3) out_tot[i] = 0.0f;
}

// ---------------------------------------------------------------------------
__global__ void k_h0(const float* __restrict__ na, const float* __restrict__ We) {
    int n = blockIdx.x;
    int c = threadIdx.x;
    float acc = 0.0f;
#pragma unroll
    for (int k = 0; k < NELn; k++)
        acc = fmaf(na[n * NELn + k], We[k * Cc + c], acc);
    g_h0[n * Cc + c] = acc;
    if (c == 0) {
        int best = 0;
        float bv = na[n * NELn];
#pragma unroll
        for (int k = 1; k < NELn; k++) {
            float v = na[n * NELn + k];
            if (v > bv) { bv = v; best = k; }
        }
        g_elem[n] = best;
    }
}

// ---------------------------------------------------------------------------
// Radial-MLP lookup-table build (w(r) is a smooth function of r only).
// ---------------------------------------------------------------------------
__global__ void k_table(const float* __restrict__ Wa1, const float* __restrict__ Wb1,
                        const float* __restrict__ Wa2, const float* __restrict__ Wb2) {
    int bin  = blockIdx.x;               // 0..TBINS
    int pass = blockIdx.y;
    const float* Wa = pass ? Wa2 : Wa1;
    const float* Wb = pass ? Wb2 : Wb1;
    float* tab      = pass ? g_tab2 : g_tab1;
    int c = threadIdx.x;                 // 0..127

    float r = fmaxf((float)bin * (RMAXf / (float)TBINS), 1e-6f);
    float x = r * (1.0f / RMAXf);
    float x2 = x * x;
    float x5 = x2 * x2 * x;
    float env = 1.0f - 21.0f * x5 + 35.0f * x5 * x - 15.0f * x5 * x2;
    if (x >= 1.0f) env = 0.0f;

    float pref = sqrtf(2.0f / RMAXf) * env / r;
    float wphase = (3.14159265358979323846f / RMAXf) * r;

    __shared__ float hid[Cc];
    if (c < Cc) {
        float h = 0.0f;
#pragma unroll
        for (int nb = 0; nb < NBn; nb++) {
            float rbn = pref * sinf((float)(nb + 1) * wphase);
            h = fmaf(rbn, Wa[nb * Cc + c], h);
        }
        hid[c] = h / (1.0f + expf(-h));
    }
    __syncthreads();

    float acc = 0.0f;
#pragma unroll
    for (int k = 0; k < Cc; k++)
        acc = fmaf(hid[k], Wb[k * 256 + c], acc);
    tab[bin * 128 + c] = acc;
}

// ---------------------------------------------------------------------------
// Edge kernel (warp-per-edge), vectorized: float4 loads + red.global.add.v4.
// Lane layout: c4 = (lane&15)*4 consecutive channels.
//   lanes 0-15  -> components Y0 (k=0) and vx (k=1)
//   lanes 16-31 -> components vy (k=2) and vz (k=3)
// Per edge: 64 red.v4 (=256 floats) vs 256 scalar atomics before.
// ---------------------------------------------------------------------------
__global__ void k_edge(const float* __restrict__ pos,
                       const float* __restrict__ shifts,
                       const int* __restrict__ ei,
                       int pass) {
    int gw = (blockIdx.x * blockDim.x + threadIdx.x) >> 5;
    int lane = threadIdx.x & 31;
    if (gw >= Ee) return;

    const float* feat = pass ? g_out0 : g_h0;
    const float* tab  = pass ? g_tab2 : g_tab1;
    float* Aout       = pass ? g_A2   : g_A;

    int snd = ei[gw];
    int rcv = ei[Ee + gw];

    float vx = pos[rcv * 3 + 0] - pos[snd * 3 + 0] + shifts[gw * 3 + 0];
    float vy = pos[rcv * 3 + 1] - pos[snd * 3 + 1] + shifts[gw * 3 + 1];
    float vz = pos[rcv * 3 + 2] - pos[snd * 3 + 2] + shifts[gw * 3 + 2];
    float r  = sqrtf(vx * vx + vy * vy + vz * vz + 1e-12f);
    if (r >= RMAXf) return;  // envelope == 0 (warp-uniform)

    float t = r * ((float)TBINS / RMAXf);
    int   i = (int)t;
    float f = t - (float)i;

    int c4   = (lane & 15) << 2;   // channel group base
    int q    = c4 >> 2;            // float4 index within 64-float block
    int half = lane >> 4;

    const float4* row0 = (const float4*)(tab + i * 128);
    const float4* row1 = row0 + 32;  // next bin (+128 floats)

    float4 f4 = *(const float4*)(feat + snd * Cc + c4);

    // w1 block (cols 64..127): needed by both halves
    float4 wa = row0[q + 16];
    float4 wb = row1[q + 16];
    float4 w1 = make_float4(wa.x + (wb.x - wa.x) * f,
                            wa.y + (wb.y - wa.y) * f,
                            wa.z + (wb.z - wa.z) * f,
                            wa.w + (wb.w - wa.w) * f);

    const float s3 = 1.7320508075688772f;
    float irs = s3 / r;
    float gx = f4.x * w1.x * irs;
    float gy = f4.y * w1.y * irs;
    float gz = f4.z * w1.z * irs;
    float gw4 = f4.w * w1.w * irs;

    float* base = Aout + rcv * (4 * Cc) + c4;
    if (half == 0) {
        // w0 block (cols 0..63): only half 0 needs it
        float4 ua = row0[q];
        float4 ub = row1[q];
        red4(base,
             f4.x * (ua.x + (ub.x - ua.x) * f),
             f4.y * (ua.y + (ub.y - ua.y) * f),
             f4.z * (ua.z + (ub.z - ua.z) * f),
             f4.w * (ua.w + (ub.w - ua.w) * f));
        red4(base + Cc, gx * vx, gy * vx, gz * vx, gw4 * vx);
    } else {
        red4(base + 2 * Cc, gx * vy, gy * vy, gz * vy, gw4 * vy);
        red4(base + 3 * Cc, gx * vz, gy * vz, gz * vz, gw4 * vz);
    }
}

// ---------------------------------------------------------------------------
// Node layer 1 (fused, one node per block — R3 version).
// ---------------------------------------------------------------------------
__global__ void k_node1(const float* __restrict__ Wmix1,
                        const float* __restrict__ Wsc1,
                        const float* __restrict__ Wps,
                        const float* __restrict__ Wpv,
                        const float* __restrict__ Wp10,
                        const float* __restrict__ Wp11,
                        const float* __restrict__ wread1)
{
    int n = blockIdx.x;
    int d = threadIdx.x;
    __shared__ float Ar[4][Cc];
    __shared__ float h0s[Cc];
    __shared__ float m0s[Cc];
    __shared__ float tm[3][Cc];
    __shared__ float red[3][2];

    const float ia = 1.0f / AVGf;
#pragma unroll
    for (int k = 0; k < 4; k++) Ar[k][d] = g_A[n * 256 + k * Cc + d] * ia;
    h0s[d] = g_h0[n * Cc + d];
    __syncthreads();

    float h1k[4];
#pragma unroll
    for (int k = 0; k < 4; k++) {
        const float* Wm = Wmix1 + (k == 0 ? 0 : Cc * Cc);  // L_OF[0..3]=0,1,1,1
        float acc = 0.0f;
#pragma unroll
        for (int c = 0; c < Cc; c++) acc = fmaf(Ar[k][c], Wm[c * Cc + d], acc);
        h1k[k] = acc;
    }

    int el = g_elem[n];
    float s = h1k[0];
    float ws0 = Wps[el * Cc + d], ws1 = Wps[NELn * Cc + el * Cc + d], ws2 = Wps[2 * NELn * Cc + el * Cc + d];
    float wv0 = Wpv[el * Cc + d], wv1 = Wpv[NELn * Cc + el * Cc + d], wv2 = Wpv[2 * NELn * Cc + el * Cc + d];
    float m0 = s * (ws0 + s * (ws1 + s * ws2));
    float gv = wv0 + s * (wv1 + s * wv2);
    m0s[d] = m0;
#pragma unroll
    for (int m = 0; m < 3; m++) tm[m][d] = h1k[m + 1] * gv;
    __syncthreads();

    float o0 = 0.0f;
    const float* Ws = Wsc1 + el * Cc * Cc;
#pragma unroll
    for (int c = 0; c < Cc; c++) o0 = fmaf(h0s[c], Ws[c * Cc + d], o0);
#pragma unroll
    for (int c = 0; c < Cc; c++) o0 = fmaf(m0s[c], Wp10[c * Cc + d], o0);
    g_out0[n * Cc + d] = o0;

    float wr = wread1[d];
#pragma unroll
    for (int m = 0; m < 3; m++) {
        float acc = 0.0f;
#pragma unroll
        for (int c = 0; c < Cc; c++) acc = fmaf(tm[m][c], Wp11[c * Cc + d], acc);
        g_out1[(n * 3 + m) * Cc + d] = acc;
        float v = acc * wr;
        v += __shfl_down_sync(0xffffffffu, v, 16);
        v += __shfl_down_sync(0xffffffffu, v, 8);
        v += __shfl_down_sync(0xffffffffu, v, 4);
        v += __shfl_down_sync(0xffffffffu, v, 2);
        v += __shfl_down_sync(0xffffffffu, v, 1);
        if ((d & 31) == 0) red[m][d >> 5] = v;
    }
    __syncthreads();
    if (d < 3) g_d1[n * 3 + d] = red[d][0] + red[d][1];
}

// ---------------------------------------------------------------------------
// Node layer 2 (fused, one node per block — R3 version).
// ---------------------------------------------------------------------------
__global__ void k_node2(const float* __restrict__ Wmix2,
                        const float* __restrict__ Wsc2,
                        const float* __restrict__ Wprod2,
                        const float* __restrict__ Wp2,
                        const float* __restrict__ Wv,
                        const float* __restrict__ Wg1,
                        const float* __restrict__ bg1,
                        const float* __restrict__ Wg2,
                        const float* __restrict__ bg2,
                        const float* __restrict__ wread2,
                        const int* __restrict__ batch,
                        const float* __restrict__ charges,
                        const float* __restrict__ pos,
                        float* __restrict__ out)
{
    int n = blockIdx.x;
    int d = threadIdx.x;
    __shared__ float Ar[4][Cc];
    __shared__ float o1s[3][Cc];
    __shared__ float tm[3][Cc];
    __shared__ float o2s[3][Cc];
    __shared__ float vhs[3][Hh];
    __shared__ float invs[Hh];
    __shared__ float g1s[Hh];
    __shared__ float af[Hh];

    const float ia = 1.0f / AVGf;
#pragma unroll
    for (int k = 0; k < 4; k++) Ar[k][d] = g_A2[n * 256 + k * Cc + d] * ia;
#pragma unroll
    for (int m = 0; m < 3; m++) o1s[m][d] = g_out1[(n * 3 + m) * Cc + d];
    __syncthreads();

    float h2k[4];
#pragma unroll
    for (int k = 0; k < 4; k++) {
        const float* Wm = Wmix2 + (k == 0 ? 0 : Cc * Cc);
        float acc = 0.0f;
#pragma unroll
        for (int c = 0; c < Cc; c++) acc = fmaf(Ar[k][c], Wm[c * Cc + d], acc);
        h2k[k] = acc;
    }

    int el = g_elem[n];
    float s2 = h2k[0];
    float wv0 = Wprod2[el * Cc + d], wv1 = Wprod2[NELn * Cc + el * Cc + d], wv2 = Wprod2[2 * NELn * Cc + el * Cc + d];
    float gv2 = wv0 + s2 * (wv1 + s2 * wv2);
#pragma unroll
    for (int m = 0; m < 3; m++) tm[m][d] = h2k[m + 1] * gv2;
    __syncthreads();

    const float* Ws = Wsc2 + el * Cc * Cc;
#pragma unroll
    for (int m = 0; m < 3; m++) {
        float acc = 0.0f;
#pragma unroll
        for (int c = 0; c < Cc; c++) acc = fmaf(o1s[m][c], Ws[c * Cc + d], acc);
#pragma unroll
        for (int c = 0; c < Cc; c++) acc = fmaf(tm[m][c], Wp2[c * Cc + d], acc);
        o2s[m][d] = acc;
    }
    __syncthreads();

    if (d < 48) {
        int m = d >> 4, h = d & 15;
        float acc = 0.0f;
#pragma unroll
        for (int c = 0; c < Cc; c++) acc = fmaf(o2s[m][c], Wv[c * Hh + h], acc);
        vhs[m][h] = acc;
    }
    __syncthreads();

    if (d < Hh) {
        float v0 = vhs[0][d], v1 = vhs[1][d], v2 = vhs[2][d];
        invs[d] = sqrtf(v0 * v0 + v1 * v1 + v2 * v2 + 1e-12f);
    }
    __syncthreads();

    if (d < Hh) {
        float pre = bg1[d];
#pragma unroll
        for (int h = 0; h < Hh; h++) pre = fmaf(invs[h], Wg1[h * Hh + d], pre);
        g1s[d] = pre / (1.0f + expf(-pre));
    }
    __syncthreads();

    if (d < Hh) {
        float a = bg2[d];
#pragma unroll
        for (int h = 0; h < Hh; h++) a = fmaf(g1s[h], Wg2[h * Hh + d], a);
        af[d] = a * wread2[d];
    }
    __syncthreads();

    if (d < 3) {
        float d2 = 0.0f;
#pragma unroll
        for (int h = 0; h < Hh; h++) d2 = fmaf(vhs[d][h], af[h], d2);
        float dip = g_d1[n * 3 + d] + d2;
        out[Gg * 3 + n * 3 + d] = dip;
        int g = batch[n];
        atomicAdd(&out[g * 3 + d], dip + charges[n] * pos[n * 3 + d]);
    }
}

// ---------------------------------------------------------------------------
// Host launcher
// ---------------------------------------------------------------------------
extern "C" void kernel_launch(void* const* d_in, const int* in_sizes, int n_in,
                              void* d_out, int out_size) {
    int iei = -1;
    for (int i = 0; i < n_in; i++) {
        if (in_sizes[i] == 2 * Ee) { iei = i; break; }
    }
    if (iei < 0) iei = 4;

    const float* na      = (const float*)d_in[0];
    const float* pos     = (const float*)d_in[1];
    const float* shifts  = (const float*)d_in[2];
    const float* charges = (const float*)d_in[3];
    const int*   ei      = (const int*)d_in[iei];
    const int*   batch   = (const int*)d_in[iei + 1];

    int w;
    if (iei == 4) {
        w = (n_in > 6 && in_sizes[6] == 1) ? 7 : 6;
    } else {
        w = 4;
    }

    const float* W_embed = (const float*)d_in[w + 0];
    const float* Wr1a    = (const float*)d_in[w + 1];
    const float* Wr1b    = (const float*)d_in[w + 2];
    const float* Wmix1   = (const float*)d_in[w + 3];
    const float* Wsc1    = (const float*)d_in[w + 4];
    const float* Wp1s    = (const float*)d_in[w + 5];
    const float* Wp1v    = (const float*)d_in[w + 6];
    const float* Wp10    = (const float*)d_in[w + 7];
    const float* Wp11    = (const float*)d_in[w + 8];
    const float* wread1  = (const float*)d_in[w + 9];
    const float* Wr2a    = (const float*)d_in[w + 10];
    const float* Wr2b    = (const float*)d_in[w + 11];
    const float* Wmix2   = (const float*)d_in[w + 12];
    const float* Wsc2    = (const float*)d_in[w + 13];
    const float* Wprod2  = (const float*)d_in[w + 14];
    const float* Wp2     = (const float*)d_in[w + 15];
    const float* Wv      = (const float*)d_in[w + 16];
    const float* Wg1     = (const float*)d_in[w + 17];
    const float* bg1     = (const float*)d_in[w + 18];
    const float* Wg2     = (const float*)d_in[w + 19];
    const float* bg2     = (const float*)d_in[w + 20];
    const float* wread2  = (const float*)d_in[w + 21];

    float* out = (float*)d_out;

    k_zero<<<2048, 256>>>(out);
    k_h0<<<Nn, Cc>>>(na, W_embed);
    dim3 tg(TBINS + 1, 2);
    k_table<<<tg, 128>>>(Wr1a, Wr1b, Wr2a, Wr2b);
    k_edge<<<Ee / 8, 256>>>(pos, shifts, ei, 0);
    k_node1<<<Nn, Cc>>>(Wmix1, Wsc1, Wp1s, Wp1v, Wp10, Wp11, wread1);
    k_edge<<<Ee / 8, 256>>>(pos, shifts, ei, 1);
    k_node2<<<Nn, Cc>>>(Wmix2, Wsc2, Wprod2, Wp2, Wv, Wg1, bg1, Wg2, bg2,
                        wread2, batch, charges, pos, out);
}

// round 6
// speedup vs baseline: 1.3757x; 1.0233x over previous
#include <cuda_runtime.h>
#include <math.h>

// Problem constants (fixed shapes)
#define Nn 8192
#define Ee 131072
#define Cc 64
#define NELn 10
#define NBn 8
#define Gg 32
#define Hh 16
#define RMAXf 5.0f
#define AVGf 16.0f
#define TBINS 8192

// Scratch (device globals; no dynamic allocation allowed)
__device__ __align__(16) float g_h0[Nn * Cc];
__device__ int   g_elem[Nn];
__device__ __align__(16) float g_A[Nn * 4 * Cc];
__device__ __align__(16) float g_A2[Nn * 4 * Cc];
__device__ __align__(16) float g_out0[Nn * Cc];
__device__ __align__(16) float g_out1[Nn * 3 * Cc];
__device__ float g_d1[Nn * 3];
// Radial-MLP lookup tables (lerp over r in [0,RMAX]); 128 outputs per bin
__device__ __align__(16) float g_tab1[(TBINS + 8) * 128];
__device__ __align__(16) float g_tab2[(TBINS + 8) * 128];
// Edge sort (counting sort by receiver node)
__device__ int    g_deg[Nn];
__device__ int    g_off[Nn + 1];
__device__ int    g_cur[Nn];
__device__ int    g_esnd[Ee];
__device__ float4 g_egeo[Ee];   // (s3*vx/r, s3*vy/r, s3*vz/r, r*TBINS/RMAX)

// ---------------------------------------------------------------------------
// Init: zero degree histogram and per-graph totals in d_out.
// ---------------------------------------------------------------------------
__global__ void k_init(float* __restrict__ out_tot) {
    int i = blockIdx.x * blockDim.x + threadIdx.x;
    if (i < Nn) g_deg[i] = 0;
    if (i < Gg * 3) out_tot[i] = 0.0f;
}

// ---------------------------------------------------------------------------
__global__ void k_h0(const float* __restrict__ na, const float* __restrict__ We) {
    int n = blockIdx.x;
    int c = threadIdx.x;
    float acc = 0.0f;
#pragma unroll
    for (int k = 0; k < NELn; k++)
        acc = fmaf(na[n * NELn + k], We[k * Cc + c], acc);
    g_h0[n * Cc + c] = acc;
    if (c == 0) {
        int best = 0;
        float bv = na[n * NELn];
#pragma unroll
        for (int k = 1; k < NELn; k++) {
            float v = na[n * NELn + k];
            if (v > bv) { bv = v; best = k; }
        }
        g_elem[n] = best;
    }
}

// ---------------------------------------------------------------------------
// Radial-MLP lookup-table build (w(r) is a smooth function of r only).
// ---------------------------------------------------------------------------
__global__ void k_table(const float* __restrict__ Wa1, const float* __restrict__ Wb1,
                        const float* __restrict__ Wa2, const float* __restrict__ Wb2) {
    int bin  = blockIdx.x;               // 0..TBINS
    int pass = blockIdx.y;
    const float* Wa = pass ? Wa2 : Wa1;
    const float* Wb = pass ? Wb2 : Wb1;
    float* tab      = pass ? g_tab2 : g_tab1;
    int c = threadIdx.x;                 // 0..127

    float r = fmaxf((float)bin * (RMAXf / (float)TBINS), 1e-6f);
    float x = r * (1.0f / RMAXf);
    float x2 = x * x;
    float x5 = x2 * x2 * x;
    float env = 1.0f - 21.0f * x5 + 35.0f * x5 * x - 15.0f * x5 * x2;
    if (x >= 1.0f) env = 0.0f;

    float pref = sqrtf(2.0f / RMAXf) * env / r;
    float wphase = (3.14159265358979323846f / RMAXf) * r;

    __shared__ float hid[Cc];
    if (c < Cc) {
        float h = 0.0f;
#pragma unroll
        for (int nb = 0; nb < NBn; nb++) {
            float rbn = pref * sinf((float)(nb + 1) * wphase);
            h = fmaf(rbn, Wa[nb * Cc + c], h);
        }
        hid[c] = h / (1.0f + expf(-h));
    }
    __syncthreads();

    float acc = 0.0f;
#pragma unroll
    for (int k = 0; k < Cc; k++)
        acc = fmaf(hid[k], Wb[k * 256 + c], acc);
    tab[bin * 128 + c] = acc;
}

// ---------------------------------------------------------------------------
// Edge degree histogram (valid edges only: r < RMAX).
// ---------------------------------------------------------------------------
__global__ void k_hist(const float* __restrict__ pos,
                       const float* __restrict__ shifts,
                       const int* __restrict__ ei) {
    int e = blockIdx.x * blockDim.x + threadIdx.x;
    if (e >= Ee) return;
    int snd = ei[e];
    int rcv = ei[Ee + e];
    float vx = pos[rcv * 3 + 0] - pos[snd * 3 + 0] + shifts[e * 3 + 0];
    float vy = pos[rcv * 3 + 1] - pos[snd * 3 + 1] + shifts[e * 3 + 1];
    float vz = pos[rcv * 3 + 2] - pos[snd * 3 + 2] + shifts[e * 3 + 2];
    float r  = sqrtf(vx * vx + vy * vy + vz * vz + 1e-12f);
    if (r < RMAXf) atomicAdd(&g_deg[rcv], 1);
}

// ---------------------------------------------------------------------------
// Exclusive prefix sum over 8192 degrees. One block, 1024 threads x 8 each.
// ---------------------------------------------------------------------------
__global__ void k_scan() {
    __shared__ int sps[1024];
    int t = threadIdx.x;
    int v[8];
    int sum = 0;
#pragma unroll
    for (int j = 0; j < 8; j++) { v[j] = g_deg[t * 8 + j]; sum += v[j]; }
    sps[t] = sum;
    __syncthreads();
    for (int o = 1; o < 1024; o <<= 1) {
        int y = (t >= o) ? sps[t - o] : 0;
        __syncthreads();
        sps[t] += y;
        __syncthreads();
    }
    int excl = sps[t] - sum;
#pragma unroll
    for (int j = 0; j < 8; j++) {
        g_off[t * 8 + j] = excl;
        g_cur[t * 8 + j] = excl;
        excl += v[j];
    }
    if (t == 1023) g_off[Nn] = sps[1023];
}

// ---------------------------------------------------------------------------
// Scatter edge payload (geometry computed ONCE, reused by both passes).
// payload = (s3*vx/r, s3*vy/r, s3*vz/r, r*TBINS/RMAX)
// ---------------------------------------------------------------------------
__global__ void k_scatter(const float* __restrict__ pos,
                          const float* __restrict__ shifts,
                          const int* __restrict__ ei) {
    int e = blockIdx.x * blockDim.x + threadIdx.x;
    if (e >= Ee) return;
    int snd = ei[e];
    int rcv = ei[Ee + e];
    float vx = pos[rcv * 3 + 0] - pos[snd * 3 + 0] + shifts[e * 3 + 0];
    float vy = pos[rcv * 3 + 1] - pos[snd * 3 + 1] + shifts[e * 3 + 1];
    float vz = pos[rcv * 3 + 2] - pos[snd * 3 + 2] + shifts[e * 3 + 2];
    float r  = sqrtf(vx * vx + vy * vy + vz * vz + 1e-12f);
    if (r >= RMAXf) return;
    int p = atomicAdd(&g_cur[rcv], 1);
    const float s3 = 1.7320508075688772f;
    float inv = s3 / r;
    g_esnd[p] = snd;
    g_egeo[p] = make_float4(vx * inv, vy * inv, vz * inv,
                            r * ((float)TBINS / RMAXf));
}

// ---------------------------------------------------------------------------
// Gather aggregation: block per node, thread per channel. No float atomics.
// A[n][k][d] accumulated in registers over the node's sorted edge segment.
// ---------------------------------------------------------------------------
__global__ void __launch_bounds__(64) k_agg(int pass) {
    const float* feat = pass ? g_out0 : g_h0;
    const float* tab  = pass ? g_tab2 : g_tab1;
    float* Aout       = pass ? g_A2   : g_A;

    int n = blockIdx.x;
    int d = threadIdx.x;
    int s = g_off[n];
    int e = g_off[n + 1];

    __shared__ int    ssnd[32];
    __shared__ float4 sgeo[32];

    float a0 = 0.0f, a1 = 0.0f, a2 = 0.0f, a3 = 0.0f;

    for (int base = s; base < e; base += 32) {
        int cnt = min(32, e - base);
        if (d < cnt) {
            ssnd[d] = g_esnd[base + d];
            sgeo[d] = g_egeo[base + d];
        }
        __syncthreads();
        for (int j = 0; j < cnt; j++) {
            float4 gv = sgeo[j];
            float t = gv.w;
            int   i = (int)t;
            float f = t - (float)i;
            const float* row = tab + i * 128;
            float r0 = row[d];
            float r1 = row[64 + d];
            float w0 = r0 + (row[128 + d] - r0) * f;
            float w1 = r1 + (row[192 + d] - r1) * f;
            float fs = feat[ssnd[j] * Cc + d];
            a0 = fmaf(fs, w0, a0);
            float g = fs * w1;
            a1 = fmaf(g, gv.x, a1);
            a2 = fmaf(g, gv.y, a2);
            a3 = fmaf(g, gv.z, a3);
        }
        __syncthreads();
    }

    float* A = Aout + n * 256;
    A[d]       = a0;
    A[64 + d]  = a1;
    A[128 + d] = a2;
    A[192 + d] = a3;
}

// ---------------------------------------------------------------------------
// Node layer 1 (fused, one node per block).
// ---------------------------------------------------------------------------
__global__ void k_node1(const float* __restrict__ Wmix1,
                        const float* __restrict__ Wsc1,
                        const float* __restrict__ Wps,
                        const float* __restrict__ Wpv,
                        const float* __restrict__ Wp10,
                        const float* __restrict__ Wp11,
                        const float* __restrict__ wread1)
{
    int n = blockIdx.x;
    int d = threadIdx.x;
    __shared__ float Ar[4][Cc];
    __shared__ float h0s[Cc];
    __shared__ float m0s[Cc];
    __shared__ float tm[3][Cc];
    __shared__ float red[3][2];

    const float ia = 1.0f / AVGf;
#pragma unroll
    for (int k = 0; k < 4; k++) Ar[k][d] = g_A[n * 256 + k * Cc + d] * ia;
    h0s[d] = g_h0[n * Cc + d];
    __syncthreads();

    float h1k[4];
#pragma unroll
    for (int k = 0; k < 4; k++) {
        const float* Wm = Wmix1 + (k == 0 ? 0 : Cc * Cc);  // L_OF[0..3]=0,1,1,1
        float acc = 0.0f;
#pragma unroll
        for (int c = 0; c < Cc; c++) acc = fmaf(Ar[k][c], Wm[c * Cc + d], acc);
        h1k[k] = acc;
    }

    int el = g_elem[n];
    float s = h1k[0];
    float ws0 = Wps[el * Cc + d], ws1 = Wps[NELn * Cc + el * Cc + d], ws2 = Wps[2 * NELn * Cc + el * Cc + d];
    float wv0 = Wpv[el * Cc + d], wv1 = Wpv[NELn * Cc + el * Cc + d], wv2 = Wpv[2 * NELn * Cc + el * Cc + d];
    float m0 = s * (ws0 + s * (ws1 + s * ws2));
    float gv = wv0 + s * (wv1 + s * wv2);
    m0s[d] = m0;
#pragma unroll
    for (int m = 0; m < 3; m++) tm[m][d] = h1k[m + 1] * gv;
    __syncthreads();

    float o0 = 0.0f;
    const float* Ws = Wsc1 + el * Cc * Cc;
#pragma unroll
    for (int c = 0; c < Cc; c++) o0 = fmaf(h0s[c], Ws[c * Cc + d], o0);
#pragma unroll
    for (int c = 0; c < Cc; c++) o0 = fmaf(m0s[c], Wp10[c * Cc + d], o0);
    g_out0[n * Cc + d] = o0;

    float wr = wread1[d];
#pragma unroll
    for (int m = 0; m < 3; m++) {
        float acc = 0.0f;
#pragma unroll
        for (int c = 0; c < Cc; c++) acc = fmaf(tm[m][c], Wp11[c * Cc + d], acc);
        g_out1[(n * 3 + m) * Cc + d] = acc;
        float v = acc * wr;
        v += __shfl_down_sync(0xffffffffu, v, 16);
        v += __shfl_down_sync(0xffffffffu, v, 8);
        v += __shfl_down_sync(0xffffffffu, v, 4);
        v += __shfl_down_sync(0xffffffffu, v, 2);
        v += __shfl_down_sync(0xffffffffu, v, 1);
        if ((d & 31) == 0) red[m][d >> 5] = v;
    }
    __syncthreads();
    if (d < 3) g_d1[n * 3 + d] = red[d][0] + red[d][1];
}

// ---------------------------------------------------------------------------
// Node layer 2 (fused, one node per block).
// ---------------------------------------------------------------------------
__global__ void k_node2(const float* __restrict__ Wmix2,
                        const float* __restrict__ Wsc2,
                        const float* __restrict__ Wprod2,
                        const float* __restrict__ Wp2,
                        const float* __restrict__ Wv,
                        const float* __restrict__ Wg1,
                        const float* __restrict__ bg1,
                        const float* __restrict__ Wg2,
                        const float* __restrict__ bg2,
                        const float* __restrict__ wread2,
                        const int* __restrict__ batch,
                        const float* __restrict__ charges,
                        const float* __restrict__ pos,
                        float* __restrict__ out)
{
    int n = blockIdx.x;
    int d = threadIdx.x;
    __shared__ float Ar[4][Cc];
    __shared__ float o1s[3][Cc];
    __shared__ float tm[3][Cc];
    __shared__ float o2s[3][Cc];
    __shared__ float vhs[3][Hh];
    __shared__ float invs[Hh];
    __shared__ float g1s[Hh];
    __shared__ float af[Hh];

    const float ia = 1.0f / AVGf;
#pragma unroll
    for (int k = 0; k < 4; k++) Ar[k][d] = g_A2[n * 256 + k * Cc + d] * ia;
#pragma unroll
    for (int m = 0; m < 3; m++) o1s[m][d] = g_out1[(n * 3 + m) * Cc + d];
    __syncthreads();

    float h2k[4];
#pragma unroll
    for (int k = 0; k < 4; k++) {
        const float* Wm = Wmix2 + (k == 0 ? 0 : Cc * Cc);
        float acc = 0.0f;
#pragma unroll
        for (int c = 0; c < Cc; c++) acc = fmaf(Ar[k][c], Wm[c * Cc + d], acc);
        h2k[k] = acc;
    }

    int el = g_elem[n];
    float s2 = h2k[0];
    float wv0 = Wprod2[el * Cc + d], wv1 = Wprod2[NELn * Cc + el * Cc + d], wv2 = Wprod2[2 * NELn * Cc + el * Cc + d];
    float gv2 = wv0 + s2 * (wv1 + s2 * wv2);
#pragma unroll
    for (int m = 0; m < 3; m++) tm[m][d] = h2k[m + 1] * gv2;
    __syncthreads();

    const float* Ws = Wsc2 + el * Cc * Cc;
#pragma unroll
    for (int m = 0; m < 3; m++) {
        float acc = 0.0f;
#pragma unroll
        for (int c = 0; c < Cc; c++) acc = fmaf(o1s[m][c], Ws[c * Cc + d], acc);
#pragma unroll
        for (int c = 0; c < Cc; c++) acc = fmaf(tm[m][c], Wp2[c * Cc + d], acc);
        o2s[m][d] = acc;
    }
    __syncthreads();

    if (d < 48) {
        int m = d >> 4, h = d & 15;
        float acc = 0.0f;
#pragma unroll
        for (int c = 0; c < Cc; c++) acc = fmaf(o2s[m][c], Wv[c * Hh + h], acc);
        vhs[m][h] = acc;
    }
    __syncthreads();

    if (d < Hh) {
        float v0 = vhs[0][d], v1 = vhs[1][d], v2 = vhs[2][d];
        invs[d] = sqrtf(v0 * v0 + v1 * v1 + v2 * v2 + 1e-12f);
    }
    __syncthreads();

    if (d < Hh) {
        float pre = bg1[d];
#pragma unroll
        for (int h = 0; h < Hh; h++) pre = fmaf(invs[h], Wg1[h * Hh + d], pre);
        g1s[d] = pre / (1.0f + expf(-pre));
    }
    __syncthreads();

    if (d < Hh) {
        float a = bg2[d];
#pragma unroll
        for (int h = 0; h < Hh; h++) a = fmaf(g1s[h], Wg2[h * Hh + d], a);
        af[d] = a * wread2[d];
    }
    __syncthreads();

    if (d < 3) {
        float d2 = 0.0f;
#pragma unroll
        for (int h = 0; h < Hh; h++) d2 = fmaf(vhs[d][h], af[h], d2);
        float dip = g_d1[n * 3 + d] + d2;
        out[Gg * 3 + n * 3 + d] = dip;
        int g = batch[n];
        atomicAdd(&out[g * 3 + d], dip + charges[n] * pos[n * 3 + d]);
    }
}

// ---------------------------------------------------------------------------
// Host launcher
// ---------------------------------------------------------------------------
extern "C" void kernel_launch(void* const* d_in, const int* in_sizes, int n_in,
                              void* d_out, int out_size) {
    int iei = -1;
    for (int i = 0; i < n_in; i++) {
        if (in_sizes[i] == 2 * Ee) { iei = i; break; }
    }
    if (iei < 0) iei = 4;

    const float* na      = (const float*)d_in[0];
    const float* pos     = (const float*)d_in[1];
    const float* shifts  = (const float*)d_in[2];
    const float* charges = (const float*)d_in[3];
    const int*   ei      = (const int*)d_in[iei];
    const int*   batch   = (const int*)d_in[iei + 1];

    int w;
    if (iei == 4) {
        w = (n_in > 6 && in_sizes[6] == 1) ? 7 : 6;
    } else {
        w = 4;
    }

    const float* W_embed = (const float*)d_in[w + 0];
    const float* Wr1a    = (const float*)d_in[w + 1];
    const float* Wr1b    = (const float*)d_in[w + 2];
    const float* Wmix1   = (const float*)d_in[w + 3];
    const float* Wsc1    = (const float*)d_in[w + 4];
    const float* Wp1s    = (const float*)d_in[w + 5];
    const float* Wp1v    = (const float*)d_in[w + 6];
    const float* Wp10    = (const float*)d_in[w + 7];
    const float* Wp11    = (const float*)d_in[w + 8];
    const float* wread1  = (const float*)d_in[w + 9];
    const float* Wr2a    = (const float*)d_in[w + 10];
    const float* Wr2b    = (const float*)d_in[w + 11];
    const float* Wmix2   = (const float*)d_in[w + 12];
    const float* Wsc2    = (const float*)d_in[w + 13];
    const float* Wprod2  = (const float*)d_in[w + 14];
    const float* Wp2     = (const float*)d_in[w + 15];
    const float* Wv      = (const float*)d_in[w + 16];
    const float* Wg1     = (const float*)d_in[w + 17];
    const float* bg1     = (const float*)d_in[w + 18];
    const float* Wg2     = (const float*)d_in[w + 19];
    const float* bg2     = (const float*)d_in[w + 20];
    const float* wread2  = (const float*)d_in[w + 21];

    float* out = (float*)d_out;

    k_init<<<32, 256>>>(out);
    k_h0<<<Nn, Cc>>>(na, W_embed);
    dim3 tg(TBINS + 1, 2);
    k_table<<<tg, 128>>>(Wr1a, Wr1b, Wr2a, Wr2b);
    k_hist<<<Ee / 256, 256>>>(pos, shifts, ei);
    k_scan<<<1, 1024>>>();
    k_scatter<<<Ee / 256, 256>>>(pos, shifts, ei);
    k_agg<<<Nn, Cc>>>(0);
    k_node1<<<Nn, Cc>>>(Wmix1, Wsc1, Wp1s, Wp1v, Wp10, Wp11, wread1);
    k_agg<<<Nn, Cc>>>(1);
    k_node2<<<Nn, Cc>>>(Wmix2, Wsc2, Wprod2, Wp2, Wv, Wg1, bg1, Wg2, bg2,
                        wread2, batch, charges, pos, out);
}